// round 2
// baseline (speedup 1.0000x reference)
#include <cuda_runtime.h>
#include <cstdint>

#define IN_F   4096
#define OUT_F  4096
#define TOKENS 8192
#define GS     128

// Scratch: dequantized tf32-rounded W (K x N, row-major) and tf32-rounded x.
__device__ float g_W[(size_t)IN_F * OUT_F];
__device__ float g_X[(size_t)TOKENS * IN_F];

__device__ __forceinline__ float f2tf32(float x) {
    uint32_t u;
    asm("cvt.rna.tf32.f32 %0, %1;" : "=r"(u) : "f"(x));
    return __uint_as_float(u);
}

// ---------------------------------------------------------------------------
// Phase 1a: dequantize packed 4-bit weights -> g_W (tf32-rounded fp32)
//   qweight[in/8][out], nibble i of word kk -> k = kk*8+i
//   qzeros [groups][out/8], nibble j of word nn -> n = nn*8+j, zero = nib+1
//   W[k][n] = scales[g][n] * (w - z), g = k/128
// ---------------------------------------------------------------------------
__global__ void dequant_kernel(const int* __restrict__ qweight,
                               const int* __restrict__ qzeros,
                               const float* __restrict__ scales) {
    const int kk = blockIdx.x;              // 0..511 (IN_F/8)
    const int g  = kk >> 4;                 // (kk*8)/128
    const int base = kk * 8;
    for (int n = threadIdx.x; n < OUT_F; n += blockDim.x) {
        uint32_t w  = (uint32_t)qweight[kk * OUT_F + n];
        uint32_t zw = (uint32_t)qzeros[g * (OUT_F / 8) + (n >> 3)];
        int z = (int)((zw >> ((n & 7) * 4)) & 15u) + 1;
        float s = scales[g * OUT_F + n];
        float* dst = g_W + (size_t)base * OUT_F + n;
#pragma unroll
        for (int i = 0; i < 8; i++) {
            int wq = (int)((w >> (4 * i)) & 15u);
            dst[(size_t)i * OUT_F] = f2tf32(s * (float)(wq - z));
        }
    }
}

// ---------------------------------------------------------------------------
// Phase 1b: tf32-round activations -> g_X
// ---------------------------------------------------------------------------
__global__ void roundx_kernel(const float4* __restrict__ x, int n4) {
    int i = blockIdx.x * blockDim.x + threadIdx.x;
    int stride = gridDim.x * blockDim.x;
    float4* dst = (float4*)g_X;
    for (; i < n4; i += stride) {
        float4 v = x[i];
        v.x = f2tf32(v.x); v.y = f2tf32(v.y);
        v.z = f2tf32(v.z); v.w = f2tf32(v.w);
        dst[i] = v;
    }
}

// ---------------------------------------------------------------------------
// Phase 2: GEMM  out[M,N] = g_X[M,K] @ g_W[K,N] + bias
// 128x128x16 CTA tile, 256 threads (8 warps as 4(m) x 2(n), warp tile 32x64),
// mma.sync.aligned.m16n8k8.tf32, cp.async double buffer.
// ---------------------------------------------------------------------------
#define BM 128
#define BN 128
#define BK 16
#define AP 20    // BK + 4  -> frag-load banks fully distinct
#define BP 136   // BN + 8  -> frag-load banks fully distinct

__device__ __forceinline__ void cp16(void* smem, const void* gmem) {
    uint32_t a = (uint32_t)__cvta_generic_to_shared(smem);
    asm volatile("cp.async.cg.shared.global [%0], [%1], 16;\n" :: "r"(a), "l"(gmem));
}

__global__ __launch_bounds__(256) void gemm_kernel(const float* __restrict__ bias,
                                                   float* __restrict__ out) {
    __shared__ __align__(16) float sA[2][BM * AP];
    __shared__ __align__(16) float sB[2][BK * BP];

    const int tid  = threadIdx.x;
    const int lane = tid & 31;
    const int wid  = tid >> 5;
    const int wm   = wid & 3;          // 0..3  (M direction)
    const int wn   = wid >> 2;         // 0..1  (N direction)
    const int m0   = blockIdx.y * BM;
    const int n0   = blockIdx.x * BN;

    const float* Ag = g_X + (size_t)m0 * IN_F;

    float acc[2][8][4];
#pragma unroll
    for (int mi = 0; mi < 2; mi++)
#pragma unroll
        for (int ni = 0; ni < 8; ni++)
#pragma unroll
            for (int j = 0; j < 4; j++) acc[mi][ni][j] = 0.0f;

    // --- async tile loaders ---
    // A: 128 rows x 16 cols, 512 float4, 2 per thread
    const int ar  = tid >> 2;                 // 0..63
    const int ac4 = (tid & 3) * 4;            // 0,4,8,12
    // B: 16 rows x 128 cols, 512 float4, 2 per thread
    const int br  = tid >> 5;                 // 0..7
    const int bc4 = (tid & 31) * 4;           // 0..124 step 4

    auto load_tiles = [&](int s, int kt) {
        const float* a0 = Ag + (size_t)ar * IN_F + kt * BK + ac4;
        cp16(&sA[s][ar * AP + ac4],        a0);
        cp16(&sA[s][(ar + 64) * AP + ac4], a0 + (size_t)64 * IN_F);
        const float* b0 = g_W + (size_t)(kt * BK + br) * OUT_F + n0 + bc4;
        cp16(&sB[s][br * BP + bc4],       b0);
        cp16(&sB[s][(br + 8) * BP + bc4], b0 + (size_t)8 * OUT_F);
    };

    load_tiles(0, 0);
    asm volatile("cp.async.commit_group;\n" ::: "memory");

    const int NK = IN_F / BK;   // 256
    for (int kt = 0; kt < NK; kt++) {
        const int s = kt & 1;
        if (kt + 1 < NK) {
            load_tiles(s ^ 1, kt + 1);
            asm volatile("cp.async.commit_group;\n" ::: "memory");
            asm volatile("cp.async.wait_group 1;\n" ::: "memory");
        } else {
            asm volatile("cp.async.wait_group 0;\n" ::: "memory");
        }
        __syncthreads();

#pragma unroll
        for (int ks = 0; ks < 2; ks++) {
            const int kb = ks * 8;
            uint32_t a[2][4], b[8][2];
#pragma unroll
            for (int mi = 0; mi < 2; mi++) {
                int r = wm * 32 + mi * 16 + (lane >> 2);
                int c = kb + (lane & 3);
                a[mi][0] = __float_as_uint(sA[s][r * AP + c]);
                a[mi][1] = __float_as_uint(sA[s][(r + 8) * AP + c]);
                a[mi][2] = __float_as_uint(sA[s][r * AP + c + 4]);
                a[mi][3] = __float_as_uint(sA[s][(r + 8) * AP + c + 4]);
            }
#pragma unroll
            for (int ni = 0; ni < 8; ni++) {
                int cb = wn * 64 + ni * 8 + (lane >> 2);
                int rb = kb + (lane & 3);
                b[ni][0] = __float_as_uint(sB[s][rb * BP + cb]);
                b[ni][1] = __float_as_uint(sB[s][(rb + 4) * BP + cb]);
            }
#pragma unroll
            for (int mi = 0; mi < 2; mi++)
#pragma unroll
                for (int ni = 0; ni < 8; ni++) {
                    asm volatile(
                        "mma.sync.aligned.m16n8k8.row.col.f32.tf32.tf32.f32 "
                        "{%0,%1,%2,%3}, {%4,%5,%6,%7}, {%8,%9}, {%0,%1,%2,%3};\n"
                        : "+f"(acc[mi][ni][0]), "+f"(acc[mi][ni][1]),
                          "+f"(acc[mi][ni][2]), "+f"(acc[mi][ni][3])
                        : "r"(a[mi][0]), "r"(a[mi][1]), "r"(a[mi][2]), "r"(a[mi][3]),
                          "r"(b[ni][0]), "r"(b[ni][1]));
                }
        }
        __syncthreads();
    }

    // --- epilogue: + bias, store fp32 ---
#pragma unroll
    for (int mi = 0; mi < 2; mi++) {
#pragma unroll
        for (int ni = 0; ni < 8; ni++) {
            int r = m0 + wm * 32 + mi * 16 + (lane >> 2);
            int c = n0 + wn * 64 + ni * 8 + (lane & 3) * 2;
            float b0 = bias[c], b1 = bias[c + 1];
            float2 v0 = make_float2(acc[mi][ni][0] + b0, acc[mi][ni][1] + b1);
            float2 v1 = make_float2(acc[mi][ni][2] + b0, acc[mi][ni][3] + b1);
            *(float2*)&out[(size_t)r * OUT_F + c]       = v0;
            *(float2*)&out[(size_t)(r + 8) * OUT_F + c] = v1;
        }
    }
}

// ---------------------------------------------------------------------------
// Launch
// inputs (metadata order): x, qweight, qzeros, scales, g_idx, bias
// ---------------------------------------------------------------------------
extern "C" void kernel_launch(void* const* d_in, const int* in_sizes, int n_in,
                              void* d_out, int out_size) {
    const float* x       = (const float*)d_in[0];
    const int*   qweight = (const int*)d_in[1];
    const int*   qzeros  = (const int*)d_in[2];
    const float* scales  = (const float*)d_in[3];
    const float* bias    = (const float*)d_in[5];
    float*       out     = (float*)d_out;

    dequant_kernel<<<IN_F / 8, 256>>>(qweight, qzeros, scales);
    roundx_kernel<<<2048, 256>>>((const float4*)x, TOKENS * IN_F / 4);

    dim3 grid(OUT_F / BN, TOKENS / BM);
    gemm_kernel<<<grid, 256>>>(bias, out);
}